// round 11
// baseline (speedup 1.0000x reference)
#include <cuda_runtime.h>
#include <mma.h>
using namespace nvcuda;

// Problem constants: N=100000, E=1600000, F=128, H=64, L=3
#define NMAX 100000
#define NPAD 100096   // padded row count (multiple of 128) for OOB-safe wmma loads
#define EMAX 1600000

// Scratch (device globals)
__device__ float g_bufY[NPAD * 64];
__device__ float g_bufZ[NPAD * 64];
__device__ float g_hA[NPAD * 64];
__device__ float g_hB[NPAD * 64];
__device__ float g_stats[4 * 128];
__device__ int2  g_edges[EMAX];
__device__ int   g_deg[NMAX];
__device__ int   g_off[NMAX];
__device__ int   g_cur[NMAX];
__device__ int   g_total;
__device__ int   g_is32;

// ---------------------------------------------------------------------------
// CSR build
// ---------------------------------------------------------------------------
__global__ void k_prep(int* __restrict__ deg, float* __restrict__ stats, int N) {
    if (blockIdx.x == 0 && threadIdx.x == 0) { g_total = 0; g_is32 = 0; }
    if (blockIdx.x == 0 && threadIdx.x < 512) stats[threadIdx.x] = 0.0f;
    int stride = gridDim.x * blockDim.x;
    for (int i = blockIdx.x * blockDim.x + threadIdx.x; i < N; i += stride)
        deg[i] = 0;
}

__global__ void k_detect(const int* __restrict__ ei, int E) {
    int stride = gridDim.x * blockDim.x;
    for (int j = blockIdx.x * blockDim.x + threadIdx.x; j < E; j += stride) {
        if (ei[2 * j + 1] != 0) { g_is32 = 1; return; }
    }
}

__global__ void k_hist(const void* __restrict__ ei, int* __restrict__ deg, int E) {
    int is32 = g_is32;
    int stride = gridDim.x * blockDim.x;
    for (int i = blockIdx.x * blockDim.x + threadIdx.x; i < E; i += stride) {
        int d = is32 ? ((const int*)ei)[E + i] : (int)((const long long*)ei)[E + i];
        atomicAdd(&deg[d], 1);
    }
}

__global__ void k_alloc(const int* __restrict__ deg, int* __restrict__ off,
                        int* __restrict__ cur, int N) {
    int stride = gridDim.x * blockDim.x;
    for (int i = blockIdx.x * blockDim.x + threadIdx.x; i < N; i += stride) {
        int o = atomicAdd(&g_total, deg[i]);
        off[i] = o;
        cur[i] = o;
    }
}

__global__ void k_fill(const void* __restrict__ ei, const float* __restrict__ ew,
                       int* __restrict__ cur, int2* __restrict__ edges, int E) {
    int is32 = g_is32;
    int stride = gridDim.x * blockDim.x;
    for (int i = blockIdx.x * blockDim.x + threadIdx.x; i < E; i += stride) {
        int s, d;
        if (is32) {
            const int* e = (const int*)ei;
            s = e[i]; d = e[E + i];
        } else {
            const long long* e = (const long long*)ei;
            s = (int)e[i]; d = (int)e[E + i];
        }
        int pos = atomicAdd(&cur[d], 1);
        edges[pos] = make_int2(s, __float_as_int(ew[i]));
    }
}

// ---------------------------------------------------------------------------
// Tensor-core GEMM (TF32x3): out[N,64] = in[N,FIN] @ W[FIN,64] (+bias)(+stats)
// 8 warps/block; warp = 16 rows x 64 cols (4x wmma 16x16x8 acc, fp32).
// TF32x3: a = ahi + alo, b = bhi + blo; acc += ahi*bhi + ahi*blo + alo*bhi
// -> residual error ~2^-21 (fp32-grade).
// APAD: A rows are padded (our buffers) -> direct global loads always safe.
//       !APAD (layer-1, A = harness x): tail block stages rows in SMEM.
// ---------------------------------------------------------------------------
template <int FIN, bool STATS, bool APAD>
__global__ __launch_bounds__(256)
void k_gemm_tc(const float* __restrict__ in, const float* __restrict__ W,
               const float* __restrict__ bias, float* __restrict__ out,
               float* __restrict__ stats, int N) {
    extern __shared__ float sm[];
    __shared__ float sstat[128];
    int tid = threadIdx.x;
    int warp = tid >> 5, lane = tid & 31;
    float* wstage = sm + warp * 16 * FIN;   // per-warp: A-tail stage + epilogue stage

    if (STATS) {
        if (tid < 128) sstat[tid] = 0.0f;
        __syncthreads();
    }

    int row0 = blockIdx.x * 128 + warp * 16;

    if (row0 < N) {
        wmma::fragment<wmma::accumulator, 16, 16, 8, float> acc[4];
        #pragma unroll
        for (int nt = 0; nt < 4; nt++) wmma::fill_fragment(acc[nt], 0.0f);

        const float* aSrc = in + (size_t)row0 * FIN;
        if (!APAD && row0 + 16 > N) {
            // tail: stage valid rows into SMEM, zero-pad the rest
            for (int i = lane; i < 16 * (FIN / 4); i += 32) {
                int r = i / (FIN / 4), c = i % (FIN / 4);
                float4 v = (row0 + r < N)
                         ? ((const float4*)(in + (size_t)(row0 + r) * FIN))[c]
                         : make_float4(0.f, 0.f, 0.f, 0.f);
                ((float4*)(wstage + r * FIN))[c] = v;
            }
            __syncwarp();
            aSrc = wstage;
        }

        wmma::fragment<wmma::matrix_a, 16, 16, 8, wmma::precision::tf32, wmma::row_major> af, ahi, alo;
        wmma::fragment<wmma::matrix_b, 16, 16, 8, wmma::precision::tf32, wmma::row_major> bf, bhi, blo;

        for (int k8 = 0; k8 < FIN / 8; k8++) {
            wmma::load_matrix_sync(af, aSrc + k8 * 8, FIN);
            #pragma unroll
            for (int i = 0; i < af.num_elements; i++) {
                float hi = wmma::__float_to_tf32(af.x[i]);
                ahi.x[i] = hi;
                alo.x[i] = wmma::__float_to_tf32(af.x[i] - hi);
            }
            #pragma unroll
            for (int nt = 0; nt < 4; nt++) {
                wmma::load_matrix_sync(bf, W + k8 * 8 * 64 + nt * 16, 64);
                #pragma unroll
                for (int i = 0; i < bf.num_elements; i++) {
                    float hi = wmma::__float_to_tf32(bf.x[i]);
                    bhi.x[i] = hi;
                    blo.x[i] = wmma::__float_to_tf32(bf.x[i] - hi);
                }
                wmma::mma_sync(acc[nt], ahi, bhi, acc[nt]);
                wmma::mma_sync(acc[nt], ahi, blo, acc[nt]);
                wmma::mma_sync(acc[nt], alo, bhi, acc[nt]);
            }
        }

        // stage 16x64 result tile in SMEM (A-stage no longer needed)
        #pragma unroll
        for (int nt = 0; nt < 4; nt++)
            wmma::store_matrix_sync(wstage + nt * 16, acc[nt], 64, wmma::mem_row_major);
        __syncwarp();

        // epilogue: bias + store + BN-stat partials. lane -> fixed 4-col group.
        int cg = lane & 15;
        float4 bv = bias ? ((const float4*)bias)[cg] : make_float4(0.f, 0.f, 0.f, 0.f);
        float s[4] = {0.f, 0.f, 0.f, 0.f};
        float q[4] = {0.f, 0.f, 0.f, 0.f};
        for (int r = lane >> 4; r < 16; r += 2) {
            if (row0 + r < N) {
                float4 v = ((const float4*)(wstage + r * 64))[cg];
                v.x += bv.x; v.y += bv.y; v.z += bv.z; v.w += bv.w;
                ((float4*)(out + (size_t)(row0 + r) * 64))[cg] = v;
                if (STATS) {
                    s[0] += v.x; q[0] += v.x * v.x;
                    s[1] += v.y; q[1] += v.y * v.y;
                    s[2] += v.z; q[2] += v.z * v.z;
                    s[3] += v.w; q[3] += v.w * v.w;
                }
            }
        }
        if (STATS) {
            #pragma unroll
            for (int j = 0; j < 4; j++) {
                atomicAdd(&sstat[cg * 4 + j], s[j]);
                atomicAdd(&sstat[64 + cg * 4 + j], q[j]);
            }
        }
    }

    if (STATS) {
        __syncthreads();
        if (tid < 128) atomicAdd(&stats[tid], sstat[tid]);
    }
}

// ---------------------------------------------------------------------------
// Gather (post-transform): z[n] = relu((1+eps)*y[n] + sum_e w_e*y[src_e] + ba)
// Warp per node (proven shape); float2 per lane; 8-deep edge unroll.
// ---------------------------------------------------------------------------
__global__ __launch_bounds__(256)
void k_gath(const float* __restrict__ y, const int* __restrict__ off,
            const int* __restrict__ deg, const int2* __restrict__ edges,
            const float* __restrict__ epsp, const float* __restrict__ ba,
            float* __restrict__ z, int N) {
    int warp = (blockIdx.x * blockDim.x + threadIdx.x) >> 5;
    int lane = threadIdx.x & 31;
    int nwarps = (gridDim.x * blockDim.x) >> 5;
    float c = 1.0f + *epsp;
    float2 bias = ((const float2*)ba)[lane];

    for (int n = warp; n < N; n += nwarps) {
        int o = off[n];
        int d = deg[n];

        float2 a = ((const float2*)(y + (size_t)n * 64))[lane];
        a.x *= c; a.y *= c;

        for (int e0 = 0; e0 < d; e0 += 32) {
            int cnt = min(32, d - e0);
            int2 ed = (lane < cnt) ? edges[o + e0 + lane] : make_int2(0, 0);
            int j = 0;
            for (; j + 8 <= cnt; j += 8) {
                int si[8]; float wi[8];
                #pragma unroll
                for (int u = 0; u < 8; u++) {
                    si[u] = __shfl_sync(0xffffffffu, ed.x, j + u);
                    wi[u] = __int_as_float(__shfl_sync(0xffffffffu, ed.y, j + u));
                }
                float2 v[8];
                #pragma unroll
                for (int u = 0; u < 8; u++)
                    v[u] = ((const float2*)(y + (size_t)si[u] * 64))[lane];
                #pragma unroll
                for (int u = 0; u < 8; u++) {
                    a.x += wi[u] * v[u].x;
                    a.y += wi[u] * v[u].y;
                }
            }
            for (; j < cnt; j++) {
                int   s = __shfl_sync(0xffffffffu, ed.x, j);
                float w = __int_as_float(__shfl_sync(0xffffffffu, ed.y, j));
                float2 v = ((const float2*)(y + (size_t)s * 64))[lane];
                a.x += w * v.x;
                a.y += w * v.y;
            }
        }

        float2 r = make_float2(fmaxf(a.x + bias.x, 0.0f), fmaxf(a.y + bias.y, 0.0f));
        ((float2*)(z + (size_t)n * 64))[lane] = r;
    }
}

// ---------------------------------------------------------------------------
// BN apply + ReLU + optional residual
// ---------------------------------------------------------------------------
__global__ void k_bn(const float4* __restrict__ h2, const float* __restrict__ stats,
                     const float* __restrict__ g, const float* __restrict__ be,
                     const float4* __restrict__ prev, float4* __restrict__ out,
                     int total4, float invN) {
    __shared__ float sscale[64], sshift[64];
    int tid = threadIdx.x;
    if (tid < 64) {
        float m = stats[tid] * invN;
        float v = stats[64 + tid] * invN - m * m;
        float sc = g[tid] * rsqrtf(v + 1e-5f);
        sscale[tid] = sc;
        sshift[tid] = be[tid] - m * sc;
    }
    __syncthreads();
    int stride = gridDim.x * blockDim.x;
    for (int i = blockIdx.x * blockDim.x + tid; i < total4; i += stride) {
        int c = (i * 4) & 63;
        float4 h = h2[i];
        float4 r;
        r.x = fmaxf(h.x * sscale[c + 0] + sshift[c + 0], 0.0f);
        r.y = fmaxf(h.y * sscale[c + 1] + sshift[c + 1], 0.0f);
        r.z = fmaxf(h.z * sscale[c + 2] + sshift[c + 2], 0.0f);
        r.w = fmaxf(h.w * sscale[c + 3] + sshift[c + 3], 0.0f);
        if (prev) {
            float4 p = prev[i];
            r.x += p.x; r.y += p.y; r.z += p.z; r.w += p.w;
        }
        out[i] = r;
    }
}

// ---------------------------------------------------------------------------
extern "C" void kernel_launch(void* const* d_in, const int* in_sizes, int n_in,
                              void* d_out, int out_size) {
    const float* x    = (const float*)d_in[0];
    const void*  ei   = d_in[1];
    const float* ew   = (const float*)d_in[2];
    const float* eps1 = (const float*)d_in[3];
    const float* W1a  = (const float*)d_in[4];
    const float* b1a  = (const float*)d_in[5];
    const float* W1b  = (const float*)d_in[6];
    const float* b1b  = (const float*)d_in[7];
    const float* g1   = (const float*)d_in[8];
    const float* be1  = (const float*)d_in[9];
    const float* epss = (const float*)d_in[10];
    const float* Wsa  = (const float*)d_in[11];
    const float* bsa  = (const float*)d_in[12];
    const float* Wsb  = (const float*)d_in[13];
    const float* bsb  = (const float*)d_in[14];
    const float* gs   = (const float*)d_in[15];
    const float* bes  = (const float*)d_in[16];

    int N   = in_sizes[0] / 128;
    int E   = in_sizes[2];
    int Lm1 = in_sizes[10];

    float *bufY, *bufZ, *hA, *hB, *stats;
    int *deg, *off, *cur;
    int2* edges;
    cudaGetSymbolAddress((void**)&bufY,  g_bufY);
    cudaGetSymbolAddress((void**)&bufZ,  g_bufZ);
    cudaGetSymbolAddress((void**)&hA,    g_hA);
    cudaGetSymbolAddress((void**)&hB,    g_hB);
    cudaGetSymbolAddress((void**)&stats, g_stats);
    cudaGetSymbolAddress((void**)&deg,   g_deg);
    cudaGetSymbolAddress((void**)&off,   g_off);
    cudaGetSymbolAddress((void**)&cur,   g_cur);
    cudaGetSymbolAddress((void**)&edges, g_edges);

    const size_t sh128 = (size_t)8 * 16 * 128 * 4;   // 64 KB (A-tail + epilogue stage)
    const size_t sh64  = (size_t)8 * 16 * 64 * 4;    // 32 KB
    cudaFuncSetAttribute(k_gemm_tc<128, false, false>, cudaFuncAttributeMaxDynamicSharedMemorySize, (int)sh128);
    cudaFuncSetAttribute(k_gemm_tc<64, false, true>,   cudaFuncAttributeMaxDynamicSharedMemorySize, (int)sh64);
    cudaFuncSetAttribute(k_gemm_tc<64, true, true>,    cudaFuncAttributeMaxDynamicSharedMemorySize, (int)sh64);

    float invN = 1.0f / (float)N;
    int gemmBlocks = (N + 127) / 128;
    int gathBlocks = 148 * 8;
    int bnBlocks   = (N * 16 + 255) / 256;

    // ---- CSR build; layer-1 GEMM hoisted (independent of CSR) ----
    k_prep<<<(N + 255) / 256, 512>>>(deg, stats, N);
    k_detect<<<512, 256>>>((const int*)ei, E);
    k_hist<<<1024, 256>>>(ei, deg, E);
    k_gemm_tc<128, false, false><<<gemmBlocks, 256, sh128>>>(x, W1a, nullptr, bufY, nullptr, N);
    k_alloc<<<(N + 255) / 256, 256>>>(deg, off, cur, N);
    k_fill<<<1024, 256>>>(ei, ew, cur, edges, E);

    // ---- layer 1 (F=128 -> H=64) ----
    k_gath<<<gathBlocks, 256>>>(bufY, off, deg, edges, eps1, b1a, bufZ, N);
    k_gemm_tc<64, true, true><<<gemmBlocks, 256, sh64>>>(bufZ, W1b, b1b, bufY, stats, N);
    k_bn<<<bnBlocks, 256>>>((const float4*)bufY, stats, g1, be1, nullptr, (float4*)hA,
                            N * 16, invN);

    // ---- layers 2..L (H=64 -> H=64, residual) ----
    const float* curh = hA;
    for (int i = 0; i < Lm1; i++) {
        float* outp = (i == Lm1 - 1) ? (float*)d_out : ((curh == hA) ? hB : hA);
        float* lstats = stats + (size_t)(i + 1) * 128;
        k_gemm_tc<64, false, true><<<gemmBlocks, 256, sh64>>>(curh, Wsa + (size_t)i * 64 * 64,
                                                              nullptr, bufY, nullptr, N);
        k_gath<<<gathBlocks, 256>>>(bufY, off, deg, edges, epss + i, bsa + i * 64,
                                    bufZ, N);
        k_gemm_tc<64, true, true><<<gemmBlocks, 256, sh64>>>(bufZ, Wsb + (size_t)i * 64 * 64,
                                                             bsb + i * 64, bufY, lstats, N);
        k_bn<<<bnBlocks, 256>>>((const float4*)bufY, lstats, gs + i * 64, bes + i * 64,
                                (const float4*)curh, (float4*)outp, N * 16, invN);
        curh = outp;
    }
}

// round 12
// speedup vs baseline: 1.2461x; 1.2461x over previous
#include <cuda_runtime.h>
#include <cuda_fp16.h>

// Problem constants: N=100000, E=1600000, F=128, H=64, L=3
#define NMAX 100000
#define NPAD 100096
#define EMAX 1600000

// Scratch (device globals)
__device__ __half g_bufYh[NPAD * 64];  // y = h@Wa in fp16 (gather operand)
__device__ float  g_bufZ[NPAD * 64];   // z = relu(agg_y + ba)
__device__ float  g_h2[NPAD * 64];     // MLP output (pre-BN)
__device__ float  g_hA[NPAD * 64];
__device__ float  g_hB[NPAD * 64];
__device__ float  g_stats[4 * 128];
__device__ int2   g_edges[EMAX];
__device__ int    g_deg[NMAX];
__device__ int    g_off[NMAX];
__device__ int    g_cur[NMAX];
__device__ int    g_total;
__device__ int    g_is32;

// ---------------------------------------------------------------------------
// CSR build
// ---------------------------------------------------------------------------
__global__ void k_prep(int* __restrict__ deg, float* __restrict__ stats, int N) {
    if (blockIdx.x == 0 && threadIdx.x == 0) { g_total = 0; g_is32 = 0; }
    if (blockIdx.x == 0 && threadIdx.x < 512) stats[threadIdx.x] = 0.0f;
    int stride = gridDim.x * blockDim.x;
    for (int i = blockIdx.x * blockDim.x + threadIdx.x; i < N; i += stride)
        deg[i] = 0;
}

__global__ void k_detect(const int* __restrict__ ei, int E) {
    int stride = gridDim.x * blockDim.x;
    for (int j = blockIdx.x * blockDim.x + threadIdx.x; j < E; j += stride) {
        if (ei[2 * j + 1] != 0) { g_is32 = 1; return; }
    }
}

__global__ void k_hist(const void* __restrict__ ei, int* __restrict__ deg, int E) {
    int is32 = g_is32;
    int stride = gridDim.x * blockDim.x;
    for (int i = blockIdx.x * blockDim.x + threadIdx.x; i < E; i += stride) {
        int d = is32 ? ((const int*)ei)[E + i] : (int)((const long long*)ei)[E + i];
        atomicAdd(&deg[d], 1);
    }
}

__global__ void k_alloc(const int* __restrict__ deg, int* __restrict__ off,
                        int* __restrict__ cur, int N) {
    int stride = gridDim.x * blockDim.x;
    for (int i = blockIdx.x * blockDim.x + threadIdx.x; i < N; i += stride) {
        int o = atomicAdd(&g_total, deg[i]);
        off[i] = o;
        cur[i] = o;
    }
}

__global__ void k_fill(const void* __restrict__ ei, const float* __restrict__ ew,
                       int* __restrict__ cur, int2* __restrict__ edges, int E) {
    int is32 = g_is32;
    int stride = gridDim.x * blockDim.x;
    for (int i = blockIdx.x * blockDim.x + threadIdx.x; i < E; i += stride) {
        int s, d;
        if (is32) {
            const int* e = (const int*)ei;
            s = e[i]; d = e[E + i];
        } else {
            const long long* e = (const long long*)ei;
            s = (int)e[i]; d = (int)e[E + i];
        }
        int pos = atomicAdd(&cur[d], 1);
        edges[pos] = make_int2(s, __float_as_int(ew[i]));
    }
}

// ---------------------------------------------------------------------------
// Tiled dense GEMM (R9 proven shape): out[N,64] = in[N,FIN] @ W[FIN,64]
// 256 threads, 64-node tile, thread tile 4x4; W + A staged in SMEM.
// OUTH: emit fp16 output (gather operand). STATS: fused BN-stat partials.
// ---------------------------------------------------------------------------
template <int FIN, bool STATS, bool OUTH>
__global__ __launch_bounds__(256)
void k_gemm(const float* __restrict__ in, const float* __restrict__ W,
            const float* __restrict__ bias, void* __restrict__ outv,
            float* __restrict__ stats, int N) {
    constexpr int P = FIN + 4;
    extern __shared__ float sm[];
    float* sW    = sm;                // FIN*64
    float* sIn   = sW + FIN * 64;     // 64*P
    float* sstat = sIn + 64 * P;      // 128

    int tid = threadIdx.x;
    int n0 = blockIdx.x * 64;

    for (int i = tid; i < FIN * 16; i += 256)
        ((float4*)sW)[i] = ((const float4*)W)[i];

    constexpr int KQ = FIN / 4;
    for (int i = tid; i < 64 * KQ; i += 256) {
        int node = i / KQ, kq = i % KQ;
        int row = n0 + node;
        float4 v = (row < N) ? ((const float4*)(in + (size_t)row * FIN))[kq]
                             : make_float4(0.f, 0.f, 0.f, 0.f);
        ((float4*)(sIn + node * P))[kq] = v;
    }
    if (STATS && tid < 128) sstat[tid] = 0.0f;
    __syncthreads();

    int tx = tid & 15, ty = tid >> 4;
    float acc[4][4];
    #pragma unroll
    for (int i = 0; i < 4; i++)
        #pragma unroll
        for (int j = 0; j < 4; j++) acc[i][j] = 0.0f;

    const float* aBase = sIn + 4 * ty * P;
    const float* bBase = sW + 4 * tx;

    #pragma unroll 2
    for (int k = 0; k < FIN; k += 4) {
        float4 b0 = *(const float4*)(bBase + (k + 0) * 64);
        float4 b1 = *(const float4*)(bBase + (k + 1) * 64);
        float4 b2 = *(const float4*)(bBase + (k + 2) * 64);
        float4 b3 = *(const float4*)(bBase + (k + 3) * 64);
        #pragma unroll
        for (int i = 0; i < 4; i++) {
            float4 a = *(const float4*)(aBase + i * P + k);
            acc[i][0] += a.x * b0.x; acc[i][1] += a.x * b0.y;
            acc[i][2] += a.x * b0.z; acc[i][3] += a.x * b0.w;
            acc[i][0] += a.y * b1.x; acc[i][1] += a.y * b1.y;
            acc[i][2] += a.y * b1.z; acc[i][3] += a.y * b1.w;
            acc[i][0] += a.z * b2.x; acc[i][1] += a.z * b2.y;
            acc[i][2] += a.z * b2.z; acc[i][3] += a.z * b2.w;
            acc[i][0] += a.w * b3.x; acc[i][1] += a.w * b3.y;
            acc[i][2] += a.w * b3.z; acc[i][3] += a.w * b3.w;
        }
    }

    float bx = 0.f, by = 0.f, bz = 0.f, bw = 0.f;
    if (bias) {
        float4 bv = *(const float4*)(bias + 4 * tx);
        bx = bv.x; by = bv.y; bz = bv.z; bw = bv.w;
    }

    float s[4] = {0.f, 0.f, 0.f, 0.f};
    float q[4] = {0.f, 0.f, 0.f, 0.f};
    #pragma unroll
    for (int i = 0; i < 4; i++) {
        int row = n0 + 4 * ty + i;
        if (row < N) {
            float4 r = make_float4(acc[i][0] + bx, acc[i][1] + by,
                                   acc[i][2] + bz, acc[i][3] + bw);
            if (OUTH) {
                __half* outH = (__half*)outv;
                __half2 h01 = __floats2half2_rn(r.x, r.y);
                __half2 h23 = __floats2half2_rn(r.z, r.w);
                uint2 pk;
                pk.x = *(unsigned*)&h01;
                pk.y = *(unsigned*)&h23;
                *(uint2*)(outH + (size_t)row * 64 + 4 * tx) = pk;
            } else {
                *(float4*)((float*)outv + (size_t)row * 64 + 4 * tx) = r;
            }
            if (STATS) {
                s[0] += r.x; q[0] += r.x * r.x;
                s[1] += r.y; q[1] += r.y * r.y;
                s[2] += r.z; q[2] += r.z * r.z;
                s[3] += r.w; q[3] += r.w * r.w;
            }
        }
    }

    if (STATS) {
        #pragma unroll
        for (int j = 0; j < 4; j++) {
            atomicAdd(&sstat[4 * tx + j], s[j]);
            atomicAdd(&sstat[64 + 4 * tx + j], q[j]);
        }
        __syncthreads();
        if (tid < 128) atomicAdd(&stats[tid], sstat[tid]);
    }
}

// ---------------------------------------------------------------------------
// Gather (fp16 operand): z[n] = relu((1+eps)*y[n] + sum_e w_e*y[src_e] + ba)
// Warp per node; __half2 per lane (2 cols), fp32 accumulate; 8-deep unroll.
// ---------------------------------------------------------------------------
__global__ __launch_bounds__(256)
void k_gath(const __half2* __restrict__ y2, const int* __restrict__ off,
            const int* __restrict__ deg, const int2* __restrict__ edges,
            const float* __restrict__ epsp, const float* __restrict__ ba,
            float* __restrict__ z, int N) {
    int warp = (blockIdx.x * blockDim.x + threadIdx.x) >> 5;
    int lane = threadIdx.x & 31;
    int nwarps = (gridDim.x * blockDim.x) >> 5;
    float c = 1.0f + *epsp;
    float2 bias = ((const float2*)ba)[lane];

    for (int n = warp; n < N; n += nwarps) {
        int o = off[n];
        int d = deg[n];

        float2 a = __half22float2(y2[(size_t)n * 32 + lane]);
        a.x *= c; a.y *= c;

        for (int e0 = 0; e0 < d; e0 += 32) {
            int cnt = min(32, d - e0);
            int2 ed = (lane < cnt) ? edges[o + e0 + lane] : make_int2(0, 0);
            int j = 0;
            for (; j + 8 <= cnt; j += 8) {
                int si[8]; float wi[8];
                #pragma unroll
                for (int u = 0; u < 8; u++) {
                    si[u] = __shfl_sync(0xffffffffu, ed.x, j + u);
                    wi[u] = __int_as_float(__shfl_sync(0xffffffffu, ed.y, j + u));
                }
                __half2 vh[8];
                #pragma unroll
                for (int u = 0; u < 8; u++)
                    vh[u] = y2[(size_t)si[u] * 32 + lane];
                #pragma unroll
                for (int u = 0; u < 8; u++) {
                    float2 v = __half22float2(vh[u]);
                    a.x += wi[u] * v.x;
                    a.y += wi[u] * v.y;
                }
            }
            for (; j < cnt; j++) {
                int   s = __shfl_sync(0xffffffffu, ed.x, j);
                float w = __int_as_float(__shfl_sync(0xffffffffu, ed.y, j));
                float2 v = __half22float2(y2[(size_t)s * 32 + lane]);
                a.x += w * v.x;
                a.y += w * v.y;
            }
        }

        float2 r = make_float2(fmaxf(a.x + bias.x, 0.0f), fmaxf(a.y + bias.y, 0.0f));
        ((float2*)(z + (size_t)n * 64))[lane] = r;
    }
}

// ---------------------------------------------------------------------------
// BN apply + ReLU + optional residual
// ---------------------------------------------------------------------------
__global__ void k_bn(const float4* __restrict__ h2, const float* __restrict__ stats,
                     const float* __restrict__ g, const float* __restrict__ be,
                     const float4* __restrict__ prev, float4* __restrict__ out,
                     int total4, float invN) {
    __shared__ float sscale[64], sshift[64];
    int tid = threadIdx.x;
    if (tid < 64) {
        float m = stats[tid] * invN;
        float v = stats[64 + tid] * invN - m * m;
        float sc = g[tid] * rsqrtf(v + 1e-5f);
        sscale[tid] = sc;
        sshift[tid] = be[tid] - m * sc;
    }
    __syncthreads();
    int stride = gridDim.x * blockDim.x;
    for (int i = blockIdx.x * blockDim.x + tid; i < total4; i += stride) {
        int c = (i * 4) & 63;
        float4 h = h2[i];
        float4 r;
        r.x = fmaxf(h.x * sscale[c + 0] + sshift[c + 0], 0.0f);
        r.y = fmaxf(h.y * sscale[c + 1] + sshift[c + 1], 0.0f);
        r.z = fmaxf(h.z * sscale[c + 2] + sshift[c + 2], 0.0f);
        r.w = fmaxf(h.w * sscale[c + 3] + sshift[c + 3], 0.0f);
        if (prev) {
            float4 p = prev[i];
            r.x += p.x; r.y += p.y; r.z += p.z; r.w += p.w;
        }
        out[i] = r;
    }
}

// ---------------------------------------------------------------------------
extern "C" void kernel_launch(void* const* d_in, const int* in_sizes, int n_in,
                              void* d_out, int out_size) {
    const float* x    = (const float*)d_in[0];
    const void*  ei   = d_in[1];
    const float* ew   = (const float*)d_in[2];
    const float* eps1 = (const float*)d_in[3];
    const float* W1a  = (const float*)d_in[4];
    const float* b1a  = (const float*)d_in[5];
    const float* W1b  = (const float*)d_in[6];
    const float* b1b  = (const float*)d_in[7];
    const float* g1   = (const float*)d_in[8];
    const float* be1  = (const float*)d_in[9];
    const float* epss = (const float*)d_in[10];
    const float* Wsa  = (const float*)d_in[11];
    const float* bsa  = (const float*)d_in[12];
    const float* Wsb  = (const float*)d_in[13];
    const float* bsb  = (const float*)d_in[14];
    const float* gs   = (const float*)d_in[15];
    const float* bes  = (const float*)d_in[16];

    int N   = in_sizes[0] / 128;
    int E   = in_sizes[2];
    int Lm1 = in_sizes[10];

    __half* bufYh;
    float *bufZ, *h2, *hA, *hB, *stats;
    int *deg, *off, *cur;
    int2* edges;
    cudaGetSymbolAddress((void**)&bufYh, g_bufYh);
    cudaGetSymbolAddress((void**)&bufZ,  g_bufZ);
    cudaGetSymbolAddress((void**)&h2,    g_h2);
    cudaGetSymbolAddress((void**)&hA,    g_hA);
    cudaGetSymbolAddress((void**)&hB,    g_hB);
    cudaGetSymbolAddress((void**)&stats, g_stats);
    cudaGetSymbolAddress((void**)&deg,   g_deg);
    cudaGetSymbolAddress((void**)&off,   g_off);
    cudaGetSymbolAddress((void**)&cur,   g_cur);
    cudaGetSymbolAddress((void**)&edges, g_edges);

    const size_t shg128 = (size_t)(128 * 64 + 64 * (128 + 4) + 128) * 4;
    const size_t shg64  = (size_t)(64 * 64 + 64 * (64 + 4) + 128) * 4;
    cudaFuncSetAttribute(k_gemm<128, false, true>, cudaFuncAttributeMaxDynamicSharedMemorySize, (int)shg128);
    cudaFuncSetAttribute(k_gemm<64, false, true>,  cudaFuncAttributeMaxDynamicSharedMemorySize, (int)shg64);
    cudaFuncSetAttribute(k_gemm<64, true, false>,  cudaFuncAttributeMaxDynamicSharedMemorySize, (int)shg64);

    float invN = 1.0f / (float)N;
    int gemmBlocks = (N + 63) / 64;
    int gathBlocks = 148 * 8;
    int bnBlocks   = (N * 16 + 255) / 256;

    // ---- CSR build; layer-1 transform hoisted (independent of CSR) ----
    k_prep<<<(N + 255) / 256, 512>>>(deg, stats, N);
    k_detect<<<512, 256>>>((const int*)ei, E);
    k_hist<<<1024, 256>>>(ei, deg, E);
    k_gemm<128, false, true><<<gemmBlocks, 256, shg128>>>(x, W1a, nullptr, bufYh, nullptr, N);
    k_alloc<<<(N + 255) / 256, 256>>>(deg, off, cur, N);
    k_fill<<<1024, 256>>>(ei, ew, cur, edges, E);

    // ---- layer 1 (F=128 -> H=64) ----
    k_gath<<<gathBlocks, 256>>>((const __half2*)bufYh, off, deg, edges, eps1, b1a, bufZ, N);
    k_gemm<64, true, false><<<gemmBlocks, 256, shg64>>>(bufZ, W1b, b1b, h2, stats, N);
    k_bn<<<bnBlocks, 256>>>((const float4*)h2, stats, g1, be1, nullptr, (float4*)hA,
                            N * 16, invN);

    // ---- layers 2..L (H=64 -> H=64, residual) ----
    const float* curh = hA;
    for (int i = 0; i < Lm1; i++) {
        float* outp = (i == Lm1 - 1) ? (float*)d_out : ((curh == hA) ? hB : hA);
        float* lstats = stats + (size_t)(i + 1) * 128;
        k_gemm<64, false, true><<<gemmBlocks, 256, shg64>>>(curh, Wsa + (size_t)i * 64 * 64,
                                                            nullptr, bufYh, nullptr, N);
        k_gath<<<gathBlocks, 256>>>((const __half2*)bufYh, off, deg, edges, epss + i,
                                    bsa + i * 64, bufZ, N);
        k_gemm<64, true, false><<<gemmBlocks, 256, shg64>>>(bufZ, Wsb + (size_t)i * 64 * 64,
                                                            bsb + i * 64, h2, lstats, N);
        k_bn<<<bnBlocks, 256>>>((const float4*)h2, lstats, gs + i * 64, bes + i * 64,
                                (const float4*)curh, (float4*)outp, N * 16, invN);
        curh = outp;
    }
}

// round 13
// speedup vs baseline: 1.3908x; 1.1161x over previous
#include <cuda_runtime.h>
#include <cuda_fp16.h>

// Problem constants: N=100000, E=1600000, F=128, H=64, L=3
#define NMAX 100000
#define NPAD 100096
#define EMAX 1600000

// Scratch (device globals)
__device__ __half g_bufYh[NPAD * 64];  // y = h@Wa in fp16 (gather operand)
__device__ float  g_h2[NPAD * 64];     // MLP output (pre-BN)
__device__ float  g_hA[NPAD * 64];
__device__ float  g_hB[NPAD * 64];
__device__ float  g_stats[4 * 128];
__device__ int2   g_edges[EMAX];
__device__ int    g_deg[NMAX];
__device__ int    g_off[NMAX];
__device__ int    g_cur[NMAX];
__device__ int    g_total;

// ---------------------------------------------------------------------------
// CSR build (edge_index dtype proven int32 in R1)
// ---------------------------------------------------------------------------
__global__ void k_prep(int* __restrict__ deg, float* __restrict__ stats, int N) {
    if (blockIdx.x == 0 && threadIdx.x == 0) g_total = 0;
    if (blockIdx.x == 0 && threadIdx.x < 512) stats[threadIdx.x] = 0.0f;
    int stride = gridDim.x * blockDim.x;
    for (int i = blockIdx.x * blockDim.x + threadIdx.x; i < N; i += stride)
        deg[i] = 0;
}

__global__ void k_hist(const int* __restrict__ ei, int* __restrict__ deg, int E) {
    int stride = gridDim.x * blockDim.x;
    for (int i = blockIdx.x * blockDim.x + threadIdx.x; i < E; i += stride)
        atomicAdd(&deg[ei[E + i]], 1);
}

__global__ void k_alloc(const int* __restrict__ deg, int* __restrict__ off,
                        int* __restrict__ cur, int N) {
    int stride = gridDim.x * blockDim.x;
    for (int i = blockIdx.x * blockDim.x + threadIdx.x; i < N; i += stride) {
        int o = atomicAdd(&g_total, deg[i]);
        off[i] = o;
        cur[i] = o;
    }
}

__global__ void k_fill(const int* __restrict__ ei, const float* __restrict__ ew,
                       int* __restrict__ cur, int2* __restrict__ edges, int E) {
    int stride = gridDim.x * blockDim.x;
    for (int i = blockIdx.x * blockDim.x + threadIdx.x; i < E; i += stride) {
        int pos = atomicAdd(&cur[ei[E + i]], 1);
        edges[pos] = make_int2(ei[i], __float_as_int(ew[i]));
    }
}

// ---------------------------------------------------------------------------
// Layer-1 transform GEMM: Yh[N,64] = fp16(x[N,128] @ W1a) (R9 proven shape)
// ---------------------------------------------------------------------------
__global__ __launch_bounds__(256)
void k_gemm128(const float* __restrict__ in, const float* __restrict__ W,
               __half* __restrict__ outH, int N) {
    constexpr int FIN = 128, P = FIN + 4;
    extern __shared__ float sm[];
    float* sW  = sm;               // 128*64
    float* sIn = sW + FIN * 64;    // 64*P

    int tid = threadIdx.x;
    int n0 = blockIdx.x * 64;

    for (int i = tid; i < FIN * 16; i += 256)
        ((float4*)sW)[i] = ((const float4*)W)[i];
    for (int i = tid; i < 64 * (FIN / 4); i += 256) {
        int node = i / (FIN / 4), kq = i % (FIN / 4);
        int row = n0 + node;
        float4 v = (row < N) ? ((const float4*)(in + (size_t)row * FIN))[kq]
                             : make_float4(0.f, 0.f, 0.f, 0.f);
        ((float4*)(sIn + node * P))[kq] = v;
    }
    __syncthreads();

    int tx = tid & 15, ty = tid >> 4;
    float acc[4][4];
    #pragma unroll
    for (int i = 0; i < 4; i++)
        #pragma unroll
        for (int j = 0; j < 4; j++) acc[i][j] = 0.0f;

    const float* aBase = sIn + 4 * ty * P;
    const float* bBase = sW + 4 * tx;

    #pragma unroll 2
    for (int k = 0; k < FIN; k += 4) {
        float4 b0 = *(const float4*)(bBase + (k + 0) * 64);
        float4 b1 = *(const float4*)(bBase + (k + 1) * 64);
        float4 b2 = *(const float4*)(bBase + (k + 2) * 64);
        float4 b3 = *(const float4*)(bBase + (k + 3) * 64);
        #pragma unroll
        for (int i = 0; i < 4; i++) {
            float4 a = *(const float4*)(aBase + i * P + k);
            acc[i][0] += a.x * b0.x; acc[i][1] += a.x * b0.y; acc[i][2] += a.x * b0.z; acc[i][3] += a.x * b0.w;
            acc[i][0] += a.y * b1.x; acc[i][1] += a.y * b1.y; acc[i][2] += a.y * b1.z; acc[i][3] += a.y * b1.w;
            acc[i][0] += a.z * b2.x; acc[i][1] += a.z * b2.y; acc[i][2] += a.z * b2.z; acc[i][3] += a.z * b2.w;
            acc[i][0] += a.w * b3.x; acc[i][1] += a.w * b3.y; acc[i][2] += a.w * b3.z; acc[i][3] += a.w * b3.w;
        }
    }

    #pragma unroll
    for (int i = 0; i < 4; i++) {
        int row = n0 + 4 * ty + i;
        if (row < N) {
            __half2 h01 = __floats2half2_rn(acc[i][0], acc[i][1]);
            __half2 h23 = __floats2half2_rn(acc[i][2], acc[i][3]);
            uint2 pk;
            pk.x = *(unsigned*)&h01;
            pk.y = *(unsigned*)&h23;
            *(uint2*)(outH + (size_t)row * 64 + 4 * tx) = pk;
        }
    }
}

// ---------------------------------------------------------------------------
// F1: fused gather + GEMM-B.
// Per 64-node block: warp w gathers nodes n0+w*8..+7 (fp16 y, fp32 accum,
// eps/bias/relu) straight into the SMEM A-tile; then 4x4 FFMA GEMM @ Wb + bb
// -> h2 (global) with fused BN-stat partials.
// ---------------------------------------------------------------------------
__global__ __launch_bounds__(256)
void k_gath_gemm(const __half2* __restrict__ y2, const int* __restrict__ off,
                 const int* __restrict__ deg, const int2* __restrict__ edges,
                 const float* __restrict__ epsp, const float* __restrict__ ba,
                 const float* __restrict__ Wb, const float* __restrict__ bb,
                 float* __restrict__ h2, float* __restrict__ stats, int N) {
    constexpr int P = 68;
    extern __shared__ float sm[];
    float* sW = sm;              // 64*64
    float* sZ = sW + 64 * 64;    // 64*P
    __shared__ float sstat[128];

    int tid = threadIdx.x;
    int warp = tid >> 5, lane = tid & 31;
    int n0 = blockIdx.x * 64;

    for (int i = tid; i < 64 * 16; i += 256)
        ((float4*)sW)[i] = ((const float4*)Wb)[i];
    if (tid < 128) sstat[tid] = 0.0f;

    float c = 1.0f + *epsp;
    float2 bias = ((const float2*)ba)[lane];

    // ---- gather phase: warp w fills rows w*8 .. w*8+7 of sZ ----
    #pragma unroll 1
    for (int i = 0; i < 8; i++) {
        int row = warp * 8 + i;
        int n = n0 + row;
        float2 a = make_float2(0.f, 0.f);
        if (n < N) {
            a = __half22float2(y2[(size_t)n * 32 + lane]);
            a.x *= c; a.y *= c;
            int o = off[n];
            int d = deg[n];
            for (int e0 = 0; e0 < d; e0 += 32) {
                int cnt = min(32, d - e0);
                int2 ed = (lane < cnt) ? edges[o + e0 + lane] : make_int2(0, 0);
                int j = 0;
                for (; j + 8 <= cnt; j += 8) {
                    int si[8]; float wi[8];
                    #pragma unroll
                    for (int u = 0; u < 8; u++) {
                        si[u] = __shfl_sync(0xffffffffu, ed.x, j + u);
                        wi[u] = __int_as_float(__shfl_sync(0xffffffffu, ed.y, j + u));
                    }
                    __half2 vh[8];
                    #pragma unroll
                    for (int u = 0; u < 8; u++)
                        vh[u] = y2[(size_t)si[u] * 32 + lane];
                    #pragma unroll
                    for (int u = 0; u < 8; u++) {
                        float2 v = __half22float2(vh[u]);
                        a.x += wi[u] * v.x;
                        a.y += wi[u] * v.y;
                    }
                }
                for (; j < cnt; j++) {
                    int   s = __shfl_sync(0xffffffffu, ed.x, j);
                    float w = __int_as_float(__shfl_sync(0xffffffffu, ed.y, j));
                    float2 v = __half22float2(y2[(size_t)s * 32 + lane]);
                    a.x += w * v.x;
                    a.y += w * v.y;
                }
            }
            a.x = fmaxf(a.x + bias.x, 0.0f);
            a.y = fmaxf(a.y + bias.y, 0.0f);
        }
        *(float2*)(sZ + row * P + 2 * lane) = a;
    }
    __syncthreads();

    // ---- GEMM phase: h2 = sZ @ Wb + bb, + stats ----
    int tx = tid & 15, ty = tid >> 4;
    float acc[4][4];
    #pragma unroll
    for (int i = 0; i < 4; i++)
        #pragma unroll
        for (int j = 0; j < 4; j++) acc[i][j] = 0.0f;

    const float* aBase = sZ + 4 * ty * P;
    const float* bBase = sW + 4 * tx;

    #pragma unroll 2
    for (int k = 0; k < 64; k += 4) {
        float4 b0 = *(const float4*)(bBase + (k + 0) * 64);
        float4 b1 = *(const float4*)(bBase + (k + 1) * 64);
        float4 b2 = *(const float4*)(bBase + (k + 2) * 64);
        float4 b3 = *(const float4*)(bBase + (k + 3) * 64);
        #pragma unroll
        for (int i = 0; i < 4; i++) {
            float4 a = *(const float4*)(aBase + i * P + k);
            acc[i][0] += a.x * b0.x; acc[i][1] += a.x * b0.y; acc[i][2] += a.x * b0.z; acc[i][3] += a.x * b0.w;
            acc[i][0] += a.y * b1.x; acc[i][1] += a.y * b1.y; acc[i][2] += a.y * b1.z; acc[i][3] += a.y * b1.w;
            acc[i][0] += a.z * b2.x; acc[i][1] += a.z * b2.y; acc[i][2] += a.z * b2.z; acc[i][3] += a.z * b2.w;
            acc[i][0] += a.w * b3.x; acc[i][1] += a.w * b3.y; acc[i][2] += a.w * b3.z; acc[i][3] += a.w * b3.w;
        }
    }

    float4 bv = ((const float4*)bb)[tx];
    float s[4] = {0.f, 0.f, 0.f, 0.f};
    float q[4] = {0.f, 0.f, 0.f, 0.f};
    #pragma unroll
    for (int i = 0; i < 4; i++) {
        int row = n0 + 4 * ty + i;
        if (row < N) {
            float4 r = make_float4(acc[i][0] + bv.x, acc[i][1] + bv.y,
                                   acc[i][2] + bv.z, acc[i][3] + bv.w);
            *(float4*)(h2 + (size_t)row * 64 + 4 * tx) = r;
            s[0] += r.x; q[0] += r.x * r.x;
            s[1] += r.y; q[1] += r.y * r.y;
            s[2] += r.z; q[2] += r.z * r.z;
            s[3] += r.w; q[3] += r.w * r.w;
        }
    }
    #pragma unroll
    for (int j = 0; j < 4; j++) {
        atomicAdd(&sstat[4 * tx + j], s[j]);
        atomicAdd(&sstat[64 + 4 * tx + j], q[j]);
    }
    __syncthreads();
    if (tid < 128) atomicAdd(&stats[tid], sstat[tid]);
}

// ---------------------------------------------------------------------------
// F2: fused BN + residual + next-layer GEMM-A.
// Stages A = prev + relu(bn(h2)) into SMEM (also written to hOut for the next
// residual), then GEMM @ Wa -> fp16 y for the next gather.
// ---------------------------------------------------------------------------
__global__ __launch_bounds__(256)
void k_bn_gemm(const float* __restrict__ h2, const float* __restrict__ stats,
               const float* __restrict__ g, const float* __restrict__ be,
               const float* __restrict__ prev, float* __restrict__ hOut,
               const float* __restrict__ Wa, __half* __restrict__ yOut,
               float invN, int N) {
    constexpr int P = 68;
    extern __shared__ float sm[];
    float* sW = sm;              // 64*64
    float* sA = sW + 64 * 64;    // 64*P
    __shared__ float sscale[64], sshift[64];

    int tid = threadIdx.x;
    int n0 = blockIdx.x * 64;

    for (int i = tid; i < 64 * 16; i += 256)
        ((float4*)sW)[i] = ((const float4*)Wa)[i];
    if (tid < 64) {
        float m = stats[tid] * invN;
        float v = stats[64 + tid] * invN - m * m;
        float sc = g[tid] * rsqrtf(v + 1e-5f);
        sscale[tid] = sc;
        sshift[tid] = be[tid] - m * sc;
    }
    __syncthreads();

    // staging: bn + relu + residual; write hOut + sA
    for (int i = tid; i < 64 * 16; i += 256) {
        int row = i >> 4, cg = i & 15;
        int gr = n0 + row;
        float4 v = make_float4(0.f, 0.f, 0.f, 0.f);
        if (gr < N) {
            v = ((const float4*)(h2 + (size_t)gr * 64))[cg];
            int c = cg * 4;
            v.x = fmaxf(v.x * sscale[c + 0] + sshift[c + 0], 0.0f);
            v.y = fmaxf(v.y * sscale[c + 1] + sshift[c + 1], 0.0f);
            v.z = fmaxf(v.z * sscale[c + 2] + sshift[c + 2], 0.0f);
            v.w = fmaxf(v.w * sscale[c + 3] + sshift[c + 3], 0.0f);
            if (prev) {
                float4 p = ((const float4*)(prev + (size_t)gr * 64))[cg];
                v.x += p.x; v.y += p.y; v.z += p.z; v.w += p.w;
            }
            ((float4*)(hOut + (size_t)gr * 64))[cg] = v;
        }
        *(float4*)(sA + row * P + cg * 4) = v;
    }
    __syncthreads();

    // GEMM: y = sA @ Wa (fp16 out, no bias)
    int tx = tid & 15, ty = tid >> 4;
    float acc[4][4];
    #pragma unroll
    for (int i = 0; i < 4; i++)
        #pragma unroll
        for (int j = 0; j < 4; j++) acc[i][j] = 0.0f;

    const float* aBase = sA + 4 * ty * P;
    const float* bBase = sW + 4 * tx;

    #pragma unroll 2
    for (int k = 0; k < 64; k += 4) {
        float4 b0 = *(const float4*)(bBase + (k + 0) * 64);
        float4 b1 = *(const float4*)(bBase + (k + 1) * 64);
        float4 b2 = *(const float4*)(bBase + (k + 2) * 64);
        float4 b3 = *(const float4*)(bBase + (k + 3) * 64);
        #pragma unroll
        for (int i = 0; i < 4; i++) {
            float4 a = *(const float4*)(aBase + i * P + k);
            acc[i][0] += a.x * b0.x; acc[i][1] += a.x * b0.y; acc[i][2] += a.x * b0.z; acc[i][3] += a.x * b0.w;
            acc[i][0] += a.y * b1.x; acc[i][1] += a.y * b1.y; acc[i][2] += a.y * b1.z; acc[i][3] += a.y * b1.w;
            acc[i][0] += a.z * b2.x; acc[i][1] += a.z * b2.y; acc[i][2] += a.z * b2.z; acc[i][3] += a.z * b2.w;
            acc[i][0] += a.w * b3.x; acc[i][1] += a.w * b3.y; acc[i][2] += a.w * b3.z; acc[i][3] += a.w * b3.w;
        }
    }

    #pragma unroll
    for (int i = 0; i < 4; i++) {
        int row = n0 + 4 * ty + i;
        if (row < N) {
            __half2 h01 = __floats2half2_rn(acc[i][0], acc[i][1]);
            __half2 h23 = __floats2half2_rn(acc[i][2], acc[i][3]);
            uint2 pk;
            pk.x = *(unsigned*)&h01;
            pk.y = *(unsigned*)&h23;
            *(uint2*)(yOut + (size_t)row * 64 + 4 * tx) = pk;
        }
    }
}

// ---------------------------------------------------------------------------
// Final BN apply + ReLU + residual -> d_out
// ---------------------------------------------------------------------------
__global__ void k_bn(const float4* __restrict__ h2, const float* __restrict__ stats,
                     const float* __restrict__ g, const float* __restrict__ be,
                     const float4* __restrict__ prev, float4* __restrict__ out,
                     int total4, float invN) {
    __shared__ float sscale[64], sshift[64];
    int tid = threadIdx.x;
    if (tid < 64) {
        float m = stats[tid] * invN;
        float v = stats[64 + tid] * invN - m * m;
        float sc = g[tid] * rsqrtf(v + 1e-5f);
        sscale[tid] = sc;
        sshift[tid] = be[tid] - m * sc;
    }
    __syncthreads();
    int stride = gridDim.x * blockDim.x;
    for (int i = blockIdx.x * blockDim.x + tid; i < total4; i += stride) {
        int c = (i * 4) & 63;
        float4 h = h2[i];
        float4 r;
        r.x = fmaxf(h.x * sscale[c + 0] + sshift[c + 0], 0.0f);
        r.y = fmaxf(h.y * sscale[c + 1] + sshift[c + 1], 0.0f);
        r.z = fmaxf(h.z * sscale[c + 2] + sshift[c + 2], 0.0f);
        r.w = fmaxf(h.w * sscale[c + 3] + sshift[c + 3], 0.0f);
        if (prev) {
            float4 p = prev[i];
            r.x += p.x; r.y += p.y; r.z += p.z; r.w += p.w;
        }
        out[i] = r;
    }
}

// ---------------------------------------------------------------------------
extern "C" void kernel_launch(void* const* d_in, const int* in_sizes, int n_in,
                              void* d_out, int out_size) {
    const float* x    = (const float*)d_in[0];
    const int*   ei   = (const int*)d_in[1];
    const float* ew   = (const float*)d_in[2];
    const float* eps1 = (const float*)d_in[3];
    const float* W1a  = (const float*)d_in[4];
    const float* b1a  = (const float*)d_in[5];
    const float* W1b  = (const float*)d_in[6];
    const float* b1b  = (const float*)d_in[7];
    const float* g1   = (const float*)d_in[8];
    const float* be1  = (const float*)d_in[9];
    const float* epss = (const float*)d_in[10];
    const float* Wsa  = (const float*)d_in[11];
    const float* bsa  = (const float*)d_in[12];
    const float* Wsb  = (const float*)d_in[13];
    const float* bsb  = (const float*)d_in[14];
    const float* gs   = (const float*)d_in[15];
    const float* bes  = (const float*)d_in[16];

    int N   = in_sizes[0] / 128;
    int E   = in_sizes[2];
    int Lm1 = in_sizes[10];

    __half* bufYh;
    float *h2, *hA, *hB, *stats;
    int *deg, *off, *cur;
    int2* edges;
    cudaGetSymbolAddress((void**)&bufYh, g_bufYh);
    cudaGetSymbolAddress((void**)&h2,    g_h2);
    cudaGetSymbolAddress((void**)&hA,    g_hA);
    cudaGetSymbolAddress((void**)&hB,    g_hB);
    cudaGetSymbolAddress((void**)&stats, g_stats);
    cudaGetSymbolAddress((void**)&deg,   g_deg);
    cudaGetSymbolAddress((void**)&off,   g_off);
    cudaGetSymbolAddress((void**)&cur,   g_cur);
    cudaGetSymbolAddress((void**)&edges, g_edges);

    const size_t shg128 = (size_t)(128 * 64 + 64 * 132) * 4;  // 66 KB
    const size_t shF    = (size_t)(64 * 64 + 64 * 68) * 4;    // 33 KB
    cudaFuncSetAttribute(k_gemm128,  cudaFuncAttributeMaxDynamicSharedMemorySize, (int)shg128);
    cudaFuncSetAttribute(k_gath_gemm, cudaFuncAttributeMaxDynamicSharedMemorySize, (int)shF);
    cudaFuncSetAttribute(k_bn_gemm,   cudaFuncAttributeMaxDynamicSharedMemorySize, (int)shF);

    float invN = 1.0f / (float)N;
    int gemmBlocks = (N + 63) / 64;
    int bnBlocks   = (N * 16 + 255) / 256;

    // ---- CSR build + layer-1 transform ----
    k_prep<<<(N + 255) / 256, 512>>>(deg, stats, N);
    k_hist<<<1024, 256>>>(ei, deg, E);
    k_gemm128<<<gemmBlocks, 256, shg128>>>(x, W1a, bufYh, N);
    k_alloc<<<(N + 255) / 256, 256>>>(deg, off, cur, N);
    k_fill<<<1024, 256>>>(ei, ew, cur, edges, E);

    // ---- layer 1: fused gather+MLP ----
    k_gath_gemm<<<gemmBlocks, 256, shF>>>((const __half2*)bufYh, off, deg, edges,
                                          eps1, b1a, W1b, b1b, h2, stats, N);

    // ---- layers 2..L ----
    const float* prevh = nullptr;   // residual base (null for layer-1 bn)
    float* houts[2] = {hA, hB};
    for (int i = 0; i < Lm1; i++) {
        float* lstats  = stats + (size_t)i * 128;        // stats of layer i+1's h2
        float* nstats  = stats + (size_t)(i + 1) * 128;
        const float* gamma = (i == 0) ? g1  : gs  + (i - 1) * 64;
        const float* beta  = (i == 0) ? be1 : bes + (i - 1) * 64;
        float* hOut = houts[i & 1];

        // bn(layer i) + residual + transform with Wsa[i] -> Yh
        k_bn_gemm<<<gemmBlocks, 256, shF>>>(h2, lstats, gamma, beta, prevh, hOut,
                                            Wsa + (size_t)i * 64 * 64, bufYh, invN, N);
        // gather + MLP of layer i+1
        k_gath_gemm<<<gemmBlocks, 256, shF>>>((const __half2*)bufYh, off, deg, edges,
                                              epss + i, bsa + i * 64,
                                              Wsb + (size_t)i * 64 * 64, bsb + i * 64,
                                              h2, nstats, N);
        prevh = hOut;
    }

    // ---- final bn + residual -> d_out ----
    k_bn<<<bnBlocks, 256>>>((const float4*)h2, stats + (size_t)Lm1 * 128,
                            gs + (Lm1 - 1) * 64, bes + (Lm1 - 1) * 64,
                            (const float4*)prevh, (float4*)d_out, N * 16, invN);
}

// round 14
// speedup vs baseline: 1.4254x; 1.0249x over previous
#include <cuda_runtime.h>
#include <cuda_fp16.h>

// Problem constants: N=100000, E=1600000, F=128, H=64, L=3
#define NMAX 100000
#define NPAD 100096
#define EMAX 1600000

// Scratch (device globals)
__device__ __half g_bufYh[NPAD * 64];  // y = h@Wa in fp16 (gather operand)
__device__ float  g_h2[NPAD * 64];     // MLP output (pre-BN)
__device__ float  g_hA[NPAD * 64];
__device__ float  g_hB[NPAD * 64];
__device__ float  g_stats[4 * 128];
__device__ int2   g_edges[EMAX];
__device__ int    g_deg[NMAX];
__device__ int    g_off[NMAX];
__device__ int    g_cur[NMAX];
__device__ int    g_total;

// ---------------------------------------------------------------------------
// CSR build (edge_index dtype proven int32 in R1)
// ---------------------------------------------------------------------------
__global__ void k_prep(int* __restrict__ deg, float* __restrict__ stats, int N) {
    if (blockIdx.x == 0 && threadIdx.x == 0) g_total = 0;
    if (blockIdx.x == 0 && threadIdx.x < 512) stats[threadIdx.x] = 0.0f;
    int stride = gridDim.x * blockDim.x;
    for (int i = blockIdx.x * blockDim.x + threadIdx.x; i < N; i += stride)
        deg[i] = 0;
}

__global__ void k_hist(const int* __restrict__ ei, int* __restrict__ deg, int E) {
    int stride = gridDim.x * blockDim.x;
    for (int i = blockIdx.x * blockDim.x + threadIdx.x; i < E; i += stride)
        atomicAdd(&deg[ei[E + i]], 1);
}

__global__ void k_alloc(const int* __restrict__ deg, int* __restrict__ off,
                        int* __restrict__ cur, int N) {
    int stride = gridDim.x * blockDim.x;
    for (int i = blockIdx.x * blockDim.x + threadIdx.x; i < N; i += stride) {
        int o = atomicAdd(&g_total, deg[i]);
        off[i] = o;
        cur[i] = o;
    }
}

__global__ void k_fill(const int* __restrict__ ei, const float* __restrict__ ew,
                       int* __restrict__ cur, int2* __restrict__ edges, int E) {
    int stride = gridDim.x * blockDim.x;
    for (int i = blockIdx.x * blockDim.x + threadIdx.x; i < E; i += stride) {
        int pos = atomicAdd(&cur[ei[E + i]], 1);
        edges[pos] = make_int2(ei[i], __float_as_int(ew[i]));
    }
}

// ---------------------------------------------------------------------------
// Layer-1 transform GEMM: Yh[N,64] = fp16(x[N,128] @ W1a) (proven shape)
// ---------------------------------------------------------------------------
__global__ __launch_bounds__(256)
void k_gemm128(const float* __restrict__ in, const float* __restrict__ W,
               __half* __restrict__ outH, int N) {
    constexpr int FIN = 128, P = FIN + 4;
    extern __shared__ float sm[];
    float* sW  = sm;               // 128*64
    float* sIn = sW + FIN * 64;    // 64*P

    int tid = threadIdx.x;
    int n0 = blockIdx.x * 64;

    for (int i = tid; i < FIN * 16; i += 256)
        ((float4*)sW)[i] = ((const float4*)W)[i];
    for (int i = tid; i < 64 * (FIN / 4); i += 256) {
        int node = i / (FIN / 4), kq = i % (FIN / 4);
        int row = n0 + node;
        float4 v = (row < N) ? ((const float4*)(in + (size_t)row * FIN))[kq]
                             : make_float4(0.f, 0.f, 0.f, 0.f);
        ((float4*)(sIn + node * P))[kq] = v;
    }
    __syncthreads();

    int tx = tid & 15, ty = tid >> 4;
    float acc[4][4];
    #pragma unroll
    for (int i = 0; i < 4; i++)
        #pragma unroll
        for (int j = 0; j < 4; j++) acc[i][j] = 0.0f;

    const float* aBase = sIn + 4 * ty * P;
    const float* bBase = sW + 4 * tx;

    #pragma unroll 2
    for (int k = 0; k < FIN; k += 4) {
        float4 b0 = *(const float4*)(bBase + (k + 0) * 64);
        float4 b1 = *(const float4*)(bBase + (k + 1) * 64);
        float4 b2 = *(const float4*)(bBase + (k + 2) * 64);
        float4 b3 = *(const float4*)(bBase + (k + 3) * 64);
        #pragma unroll
        for (int i = 0; i < 4; i++) {
            float4 a = *(const float4*)(aBase + i * P + k);
            acc[i][0] += a.x * b0.x; acc[i][1] += a.x * b0.y; acc[i][2] += a.x * b0.z; acc[i][3] += a.x * b0.w;
            acc[i][0] += a.y * b1.x; acc[i][1] += a.y * b1.y; acc[i][2] += a.y * b1.z; acc[i][3] += a.y * b1.w;
            acc[i][0] += a.z * b2.x; acc[i][1] += a.z * b2.y; acc[i][2] += a.z * b2.z; acc[i][3] += a.z * b2.w;
            acc[i][0] += a.w * b3.x; acc[i][1] += a.w * b3.y; acc[i][2] += a.w * b3.z; acc[i][3] += a.w * b3.w;
        }
    }

    #pragma unroll
    for (int i = 0; i < 4; i++) {
        int row = n0 + 4 * ty + i;
        if (row < N) {
            __half2 h01 = __floats2half2_rn(acc[i][0], acc[i][1]);
            __half2 h23 = __floats2half2_rn(acc[i][2], acc[i][3]);
            uint2 pk;
            pk.x = *(unsigned*)&h01;
            pk.y = *(unsigned*)&h23;
            *(uint2*)(outH + (size_t)row * 64 + 4 * tx) = pk;
        }
    }
}

// ---------------------------------------------------------------------------
// F1: fused gather + GEMM-B.
// Per 64-node block: warp w gathers nodes n0+w*8..+7 (fp16 y, fp32 accum,
// eps/bias/relu) straight into the SMEM A-tile; then 4x4 FFMA GEMM @ Wb + bb
// -> h2 (global) with fused BN-stat partials.
// ---------------------------------------------------------------------------
__global__ __launch_bounds__(256)
void k_gath_gemm(const __half2* __restrict__ y2, const int* __restrict__ off,
                 const int* __restrict__ deg, const int2* __restrict__ edges,
                 const float* __restrict__ epsp, const float* __restrict__ ba,
                 const float* __restrict__ Wb, const float* __restrict__ bb,
                 float* __restrict__ h2, float* __restrict__ stats, int N) {
    constexpr int P = 68;
    extern __shared__ float sm[];
    float* sW = sm;              // 64*64
    float* sZ = sW + 64 * 64;    // 64*P
    __shared__ float sstat[128];

    int tid = threadIdx.x;
    int warp = tid >> 5, lane = tid & 31;
    int n0 = blockIdx.x * 64;

    for (int i = tid; i < 64 * 16; i += 256)
        ((float4*)sW)[i] = ((const float4*)Wb)[i];
    if (tid < 128) sstat[tid] = 0.0f;

    float c = 1.0f + *epsp;
    float2 bias = ((const float2*)ba)[lane];

    // ---- gather phase: warp w fills rows w*8 .. w*8+7 of sZ ----
    #pragma unroll 1
    for (int i = 0; i < 8; i++) {
        int row = warp * 8 + i;
        int n = n0 + row;
        float2 a = make_float2(0.f, 0.f);
        if (n < N) {
            a = __half22float2(y2[(size_t)n * 32 + lane]);
            a.x *= c; a.y *= c;
            int o = off[n];
            int d = deg[n];
            for (int e0 = 0; e0 < d; e0 += 32) {
                int cnt = min(32, d - e0);
                int2 ed = (lane < cnt) ? edges[o + e0 + lane] : make_int2(0, 0);
                int j = 0;
                for (; j + 8 <= cnt; j += 8) {
                    int si[8]; float wi[8];
                    #pragma unroll
                    for (int u = 0; u < 8; u++) {
                        si[u] = __shfl_sync(0xffffffffu, ed.x, j + u);
                        wi[u] = __int_as_float(__shfl_sync(0xffffffffu, ed.y, j + u));
                    }
                    __half2 vh[8];
                    #pragma unroll
                    for (int u = 0; u < 8; u++)
                        vh[u] = y2[(size_t)si[u] * 32 + lane];
                    #pragma unroll
                    for (int u = 0; u < 8; u++) {
                        float2 v = __half22float2(vh[u]);
                        a.x += wi[u] * v.x;
                        a.y += wi[u] * v.y;
                    }
                }
                for (; j < cnt; j++) {
                    int   s = __shfl_sync(0xffffffffu, ed.x, j);
                    float w = __int_as_float(__shfl_sync(0xffffffffu, ed.y, j));
                    float2 v = __half22float2(y2[(size_t)s * 32 + lane]);
                    a.x += w * v.x;
                    a.y += w * v.y;
                }
            }
            a.x = fmaxf(a.x + bias.x, 0.0f);
            a.y = fmaxf(a.y + bias.y, 0.0f);
        }
        *(float2*)(sZ + row * P + 2 * lane) = a;
    }
    __syncthreads();

    // ---- GEMM phase: h2 = sZ @ Wb + bb, + stats ----
    int tx = tid & 15, ty = tid >> 4;
    float acc[4][4];
    #pragma unroll
    for (int i = 0; i < 4; i++)
        #pragma unroll
        for (int j = 0; j < 4; j++) acc[i][j] = 0.0f;

    const float* aBase = sZ + 4 * ty * P;
    const float* bBase = sW + 4 * tx;

    #pragma unroll 2
    for (int k = 0; k < 64; k += 4) {
        float4 b0 = *(const float4*)(bBase + (k + 0) * 64);
        float4 b1 = *(const float4*)(bBase + (k + 1) * 64);
        float4 b2 = *(const float4*)(bBase + (k + 2) * 64);
        float4 b3 = *(const float4*)(bBase + (k + 3) * 64);
        #pragma unroll
        for (int i = 0; i < 4; i++) {
            float4 a = *(const float4*)(aBase + i * P + k);
            acc[i][0] += a.x * b0.x; acc[i][1] += a.x * b0.y; acc[i][2] += a.x * b0.z; acc[i][3] += a.x * b0.w;
            acc[i][0] += a.y * b1.x; acc[i][1] += a.y * b1.y; acc[i][2] += a.y * b1.z; acc[i][3] += a.y * b1.w;
            acc[i][0] += a.z * b2.x; acc[i][1] += a.z * b2.y; acc[i][2] += a.z * b2.z; acc[i][3] += a.z * b2.w;
            acc[i][0] += a.w * b3.x; acc[i][1] += a.w * b3.y; acc[i][2] += a.w * b3.z; acc[i][3] += a.w * b3.w;
        }
    }

    float4 bv = ((const float4*)bb)[tx];
    float s[4] = {0.f, 0.f, 0.f, 0.f};
    float q[4] = {0.f, 0.f, 0.f, 0.f};
    #pragma unroll
    for (int i = 0; i < 4; i++) {
        int row = n0 + 4 * ty + i;
        if (row < N) {
            float4 r = make_float4(acc[i][0] + bv.x, acc[i][1] + bv.y,
                                   acc[i][2] + bv.z, acc[i][3] + bv.w);
            *(float4*)(h2 + (size_t)row * 64 + 4 * tx) = r;
            s[0] += r.x; q[0] += r.x * r.x;
            s[1] += r.y; q[1] += r.y * r.y;
            s[2] += r.z; q[2] += r.z * r.z;
            s[3] += r.w; q[3] += r.w * r.w;
        }
    }
    #pragma unroll
    for (int j = 0; j < 4; j++) {
        atomicAdd(&sstat[4 * tx + j], s[j]);
        atomicAdd(&sstat[64 + 4 * tx + j], q[j]);
    }
    __syncthreads();
    if (tid < 128) atomicAdd(&stats[tid], sstat[tid]);
}

// ---------------------------------------------------------------------------
// F2: fused BN + residual + next-layer GEMM-A.
// ---------------------------------------------------------------------------
__global__ __launch_bounds__(256)
void k_bn_gemm(const float* __restrict__ h2, const float* __restrict__ stats,
               const float* __restrict__ g, const float* __restrict__ be,
               const float* __restrict__ prev, float* __restrict__ hOut,
               const float* __restrict__ Wa, __half* __restrict__ yOut,
               float invN, int N) {
    constexpr int P = 68;
    extern __shared__ float sm[];
    float* sW = sm;              // 64*64
    float* sA = sW + 64 * 64;    // 64*P
    __shared__ float sscale[64], sshift[64];

    int tid = threadIdx.x;
    int n0 = blockIdx.x * 64;

    for (int i = tid; i < 64 * 16; i += 256)
        ((float4*)sW)[i] = ((const float4*)Wa)[i];
    if (tid < 64) {
        float m = stats[tid] * invN;
        float v = stats[64 + tid] * invN - m * m;
        float sc = g[tid] * rsqrtf(v + 1e-5f);
        sscale[tid] = sc;
        sshift[tid] = be[tid] - m * sc;
    }
    __syncthreads();

    for (int i = tid; i < 64 * 16; i += 256) {
        int row = i >> 4, cg = i & 15;
        int gr = n0 + row;
        float4 v = make_float4(0.f, 0.f, 0.f, 0.f);
        if (gr < N) {
            v = ((const float4*)(h2 + (size_t)gr * 64))[cg];
            int c = cg * 4;
            v.x = fmaxf(v.x * sscale[c + 0] + sshift[c + 0], 0.0f);
            v.y = fmaxf(v.y * sscale[c + 1] + sshift[c + 1], 0.0f);
            v.z = fmaxf(v.z * sscale[c + 2] + sshift[c + 2], 0.0f);
            v.w = fmaxf(v.w * sscale[c + 3] + sshift[c + 3], 0.0f);
            if (prev) {
                float4 p = ((const float4*)(prev + (size_t)gr * 64))[cg];
                v.x += p.x; v.y += p.y; v.z += p.z; v.w += p.w;
            }
            ((float4*)(hOut + (size_t)gr * 64))[cg] = v;
        }
        *(float4*)(sA + row * P + cg * 4) = v;
    }
    __syncthreads();

    int tx = tid & 15, ty = tid >> 4;
    float acc[4][4];
    #pragma unroll
    for (int i = 0; i < 4; i++)
        #pragma unroll
        for (int j = 0; j < 4; j++) acc[i][j] = 0.0f;

    const float* aBase = sA + 4 * ty * P;
    const float* bBase = sW + 4 * tx;

    #pragma unroll 2
    for (int k = 0; k < 64; k += 4) {
        float4 b0 = *(const float4*)(bBase + (k + 0) * 64);
        float4 b1 = *(const float4*)(bBase + (k + 1) * 64);
        float4 b2 = *(const float4*)(bBase + (k + 2) * 64);
        float4 b3 = *(const float4*)(bBase + (k + 3) * 64);
        #pragma unroll
        for (int i = 0; i < 4; i++) {
            float4 a = *(const float4*)(aBase + i * P + k);
            acc[i][0] += a.x * b0.x; acc[i][1] += a.x * b0.y; acc[i][2] += a.x * b0.z; acc[i][3] += a.x * b0.w;
            acc[i][0] += a.y * b1.x; acc[i][1] += a.y * b1.y; acc[i][2] += a.y * b1.z; acc[i][3] += a.y * b1.w;
            acc[i][0] += a.z * b2.x; acc[i][1] += a.z * b2.y; acc[i][2] += a.z * b2.z; acc[i][3] += a.z * b2.w;
            acc[i][0] += a.w * b3.x; acc[i][1] += a.w * b3.y; acc[i][2] += a.w * b3.z; acc[i][3] += a.w * b3.w;
        }
    }

    #pragma unroll
    for (int i = 0; i < 4; i++) {
        int row = n0 + 4 * ty + i;
        if (row < N) {
            __half2 h01 = __floats2half2_rn(acc[i][0], acc[i][1]);
            __half2 h23 = __floats2half2_rn(acc[i][2], acc[i][3]);
            uint2 pk;
            pk.x = *(unsigned*)&h01;
            pk.y = *(unsigned*)&h23;
            *(uint2*)(yOut + (size_t)row * 64 + 4 * tx) = pk;
        }
    }
}

// ---------------------------------------------------------------------------
// Final BN apply + ReLU + residual -> d_out
// ---------------------------------------------------------------------------
__global__ void k_bn(const float4* __restrict__ h2, const float* __restrict__ stats,
                     const float* __restrict__ g, const float* __restrict__ be,
                     const float4* __restrict__ prev, float4* __restrict__ out,
                     int total4, float invN) {
    __shared__ float sscale[64], sshift[64];
    int tid = threadIdx.x;
    if (tid < 64) {
        float m = stats[tid] * invN;
        float v = stats[64 + tid] * invN - m * m;
        float sc = g[tid] * rsqrtf(v + 1e-5f);
        sscale[tid] = sc;
        sshift[tid] = be[tid] - m * sc;
    }
    __syncthreads();
    int stride = gridDim.x * blockDim.x;
    for (int i = blockIdx.x * blockDim.x + tid; i < total4; i += stride) {
        int c = (i * 4) & 63;
        float4 h = h2[i];
        float4 r;
        r.x = fmaxf(h.x * sscale[c + 0] + sshift[c + 0], 0.0f);
        r.y = fmaxf(h.y * sscale[c + 1] + sshift[c + 1], 0.0f);
        r.z = fmaxf(h.z * sscale[c + 2] + sshift[c + 2], 0.0f);
        r.w = fmaxf(h.w * sscale[c + 3] + sshift[c + 3], 0.0f);
        if (prev) {
            float4 p = prev[i];
            r.x += p.x; r.y += p.y; r.z += p.z; r.w += p.w;
        }
        out[i] = r;
    }
}

// ---------------------------------------------------------------------------
extern "C" void kernel_launch(void* const* d_in, const int* in_sizes, int n_in,
                              void* d_out, int out_size) {
    const float* x    = (const float*)d_in[0];
    const int*   ei   = (const int*)d_in[1];
    const float* ew   = (const float*)d_in[2];
    const float* eps1 = (const float*)d_in[3];
    const float* W1a  = (const float*)d_in[4];
    const float* b1a  = (const float*)d_in[5];
    const float* W1b  = (const float*)d_in[6];
    const float* b1b  = (const float*)d_in[7];
    const float* g1   = (const float*)d_in[8];
    const float* be1  = (const float*)d_in[9];
    const float* epss = (const float*)d_in[10];
    const float* Wsa  = (const float*)d_in[11];
    const float* bsa  = (const float*)d_in[12];
    const float* Wsb  = (const float*)d_in[13];
    const float* bsb  = (const float*)d_in[14];
    const float* gs   = (const float*)d_in[15];
    const float* bes  = (const float*)d_in[16];

    int N   = in_sizes[0] / 128;
    int E   = in_sizes[2];
    int Lm1 = in_sizes[10];

    __half* bufYh;
    float *h2, *hA, *hB, *stats;
    int *deg, *off, *cur;
    int2* edges;
    cudaGetSymbolAddress((void**)&bufYh, g_bufYh);
    cudaGetSymbolAddress((void**)&h2,    g_h2);
    cudaGetSymbolAddress((void**)&hA,    g_hA);
    cudaGetSymbolAddress((void**)&hB,    g_hB);
    cudaGetSymbolAddress((void**)&stats, g_stats);
    cudaGetSymbolAddress((void**)&deg,   g_deg);
    cudaGetSymbolAddress((void**)&off,   g_off);
    cudaGetSymbolAddress((void**)&cur,   g_cur);
    cudaGetSymbolAddress((void**)&edges, g_edges);

    const size_t shg128 = (size_t)(128 * 64 + 64 * 132) * 4;  // 66 KB
    const size_t shF    = (size_t)(64 * 64 + 64 * 68) * 4;    // 33 KB
    cudaFuncSetAttribute(k_gemm128,  cudaFuncAttributeMaxDynamicSharedMemorySize, (int)shg128);
    cudaFuncSetAttribute(k_gath_gemm, cudaFuncAttributeMaxDynamicSharedMemorySize, (int)shF);
    cudaFuncSetAttribute(k_bn_gemm,   cudaFuncAttributeMaxDynamicSharedMemorySize, (int)shF);

    float invN = 1.0f / (float)N;
    int gemmBlocks = (N + 63) / 64;
    int bnBlocks   = (N * 16 + 255) / 256;

    // ---- fork: k_gemm128 (x@W1a) runs concurrently with the CSR build ----
    // Host objects are created per call and intentionally NOT destroyed:
    // kernel_launch's host code runs only twice (correctness + capture), and
    // destroying a stream that participated in an active capture would
    // invalidate the capture. GPU work is identical on every call.
    cudaStream_t s2;
    cudaStreamCreateWithFlags(&s2, cudaStreamNonBlocking);
    cudaEvent_t evFork, evJoin;
    cudaEventCreateWithFlags(&evFork, cudaEventDisableTiming);
    cudaEventCreateWithFlags(&evJoin, cudaEventDisableTiming);

    cudaEventRecord(evFork, 0);
    cudaStreamWaitEvent(s2, evFork, 0);
    k_gemm128<<<gemmBlocks, 256, shg128, s2>>>(x, W1a, bufYh, N);
    cudaEventRecord(evJoin, s2);

    // ---- CSR build on the main stream (independent of gemm128) ----
    k_prep<<<(N + 255) / 256, 512>>>(deg, stats, N);
    k_hist<<<1024, 256>>>(ei, deg, E);
    k_alloc<<<(N + 255) / 256, 256>>>(deg, off, cur, N);
    k_fill<<<1024, 256>>>(ei, ew, cur, edges, E);

    // ---- join: layer-1 gather needs both CSR and Yh ----
    cudaStreamWaitEvent(0, evJoin, 0);

    // ---- layer 1: fused gather+MLP ----
    k_gath_gemm<<<gemmBlocks, 256, shF>>>((const __half2*)bufYh, off, deg, edges,
                                          eps1, b1a, W1b, b1b, h2, stats, N);

    // ---- layers 2..L ----
    const float* prevh = nullptr;
    float* houts[2] = {hA, hB};
    for (int i = 0; i < Lm1; i++) {
        float* lstats  = stats + (size_t)i * 128;
        float* nstats  = stats + (size_t)(i + 1) * 128;
        const float* gamma = (i == 0) ? g1  : gs  + (i - 1) * 64;
        const float* beta  = (i == 0) ? be1 : bes + (i - 1) * 64;
        float* hOut = houts[i & 1];

        k_bn_gemm<<<gemmBlocks, 256, shF>>>(h2, lstats, gamma, beta, prevh, hOut,
                                            Wsa + (size_t)i * 64 * 64, bufYh, invN, N);
        k_gath_gemm<<<gemmBlocks, 256, shF>>>((const __half2*)bufYh, off, deg, edges,
                                              epss + i, bsa + i * 64,
                                              Wsb + (size_t)i * 64 * 64, bsb + i * 64,
                                              h2, nstats, N);
        prevh = hOut;
    }

    // ---- final bn + residual -> d_out ----
    k_bn<<<bnBlocks, 256>>>((const float4*)h2, stats + (size_t)Lm1 * 128,
                            gs + (Lm1 - 1) * 64, bes + (Lm1 - 1) * 64,
                            (const float4*)prevh, (float4*)d_out, N * 16, invN);
}